// round 16
// baseline (speedup 1.0000x reference)
#include <cuda_runtime.h>

#define BATCH 8
#define NPIX 65536
#define INV_N (1.0f/65536.0f)
#define FULL 0xffffffffu

// accumulators + rope table (reset/refilled every launch by k0 -> deterministic)
__device__ float  g_ksum[BATCH*64];     // [b][kchan]
__device__ float  g_kv[BATCH*1024];     // [b][h][d][e]
__device__ float2 g_cs[256*32];         // [wcoord][j] cos/sin
// rope'd Q scratch, (b, n, 64) row-major; fully overwritten by k1 every launch
__device__ float  g_q[(size_t)BATCH*NPIX*64];

// ---------------------------------------------------------------------------
__global__ void k0_init() {
    int t = blockIdx.x * 256 + threadIdx.x;     // 0..8191
    if (t < BATCH*64) g_ksum[t] = 0.f;
    g_kv[t] = 0.f;
    int wc = t >> 5, j = t & 31;
    float theta = exp2f(-(float)j * (13.287712379549449f / 32.0f));
    float a = (float)wc * theta;
    g_cs[t] = make_float2(cosf(a), sinf(a));
}

// ---------------------------------------------------------------------------
// Raw row load (no shfl at load time). Thread owns columns (COLV, COLV+1).
#define LDRAW(rr, RAW, EL, ER) do {                                            \
    int _r = (rr); bool _ok = ((unsigned)_r < 256u);                           \
    RAW = make_float2(0.f, 0.f); EL = 0.f; ER = 0.f;                           \
    if (_ok) {                                                                 \
        RAW = __ldg((const float2*)&xc[_r*256 + COLV]);                        \
        if (lane == 0 && LOKC)  EL = __ldg(&xc[_r*256 + COLV - 1]);            \
        if (lane == 31 && ROKC) ER = __ldg(&xc[_r*256 + COLV + 2]);            \
    } } while(0)

// Materialize (l, c, r) from a raw row at consumption time (shfl here).
#define MAT(RAW, EL, ER, L, C, R) do {                                         \
    float _l = __shfl_up_sync(FULL, RAW.y, 1);                                 \
    float _rv = __shfl_down_sync(FULL, RAW.x, 1);                              \
    if (lane == 0)  _l = EL;                                                   \
    if (lane == 31) _rv = ER;                                                  \
    (L) = _l; (C) = RAW; (R) = _rv; } while(0)

// complex rotation step: cs *= rot
#define CSROT(cs, rot) do {                                                    \
    float _x = cs.x*rot.x - cs.y*rot.y;                                        \
    cs.y = cs.x*rot.y + cs.y*rot.x;                                            \
    cs.x = _x; } while(0)

// ---------------------------------------------------------------------------
// Pass 1 (fused Q+K, per-batch launch): one conv sweep per image-row quarter.
// Warps 0/2: Q halves -> elu, rope, stream to g_q.
// Warps 1/3: K halves -> elu, rope, accumulate ksum + per-head kv (V via smem).
// Depth-1 raw row deferral; reduction buffers ALIAS vsm (dead after loop).
__global__ void __launch_bounds__(128) k1_qkv(
    const float* __restrict__ x,
    const float* __restrict__ qk_w,
    const float* __restrict__ qk_b,
    int b)
{
    const int seg = blockIdx.x, ch = blockIdx.y;
    const int t = threadIdx.x;
    const int lane = t & 31;            // j: channel pair index
    const int w_id = t >> 5;
    const int p   = w_id >> 1;          // row parity (column half)
    const int isK = w_id & 1;
    const int j = lane;
    const int h = j >> 3;
    const float* xb = x + (size_t)b * (64*NPIX);
    const float* xc = xb + (size_t)(ch >> 1) * NPIX;

    const int COLV = p*128 + (isK ? 64 : 0) + 2*j;
    const bool LOKC = (COLV > 0);
    const bool ROKC = (COLV + 2 < 256);

    // V staging: rows ni in [ch*512+seg*128, +128) -> 8192 floats, coalesced.
    // After the main loop vsm is dead; reduction buffers alias it (saves 8.5KB).
    __shared__ __align__(16) float4 vsm[2048];  // 32KB
    float* sred  = (float*)vsm;          // [32*64] = 2048 floats
    float* sred2 = ((float*)vsm) + 2048; // [128]
    {
        const float4* vsrc = (const float4*)(xb + (size_t)ch*32768 + (size_t)seg*8192);
        for (int i = t; i < 2048; i += 128) vsm[i] = __ldg(vsrc + i);
    }

    float w[9];
#pragma unroll
    for (int i = 0; i < 9; i++) w[i] = __ldg(&qk_w[ch*9 + i]);
    const float bias = __ldg(&qk_b[ch]);

    const int rs = seg * 64;

    // window rows rs-1..rs+1 materialized; raw row rs+2 pending (depth 1)
    float l0,r0,l1,r1,l2,r2; float2 c0,c1,c2;
    float2 rA; float rAl, rAr;
    {
        float2 rw; float el, er;
        LDRAW(rs-1, rw, el, er); MAT(rw, el, er, l0, c0, r0);
        LDRAW(rs,   rw, el, er); MAT(rw, el, er, l1, c1, r1);
        LDRAW(rs+1, rw, el, er); MAT(rw, el, er, l2, c2, r2);
        LDRAW(rs+2, rA, rAl, rAr);
    }

    // rope phase: cs = cs(col0), rot = cs(2) (col advances by 2 per iteration)
    float2 cs  = __ldg(&g_cs[((2*rs + p) & 255)*32 + j]);
    const float2 rot = __ldg(&g_cs[2*32 + j]);

    float acc0[16], acc1[16];
#pragma unroll
    for (int e = 0; e < 16; e++) { acc0[e] = 0.f; acc1[e] = 0.f; }
    float ksum0 = 0.f, ksum1 = 0.f;

    float* qdst = g_q + ((size_t)b*NPIX + (size_t)ch*512 + 2*rs + p)*64 + 2*j;

    __syncthreads();    // vsm ready

    for (int ii = 0; ii < 64; ii++) {
        const int hi = rs + ii;

        float a0 = bias + w[0]*l0   + w[1]*c0.x + w[2]*c0.y
                        + w[3]*l1   + w[4]*c1.x + w[5]*c1.y
                        + w[6]*l2   + w[7]*c2.x + w[8]*c2.y;
        float a1 = bias + w[0]*c0.x + w[1]*c0.y + w[2]*r0
                        + w[3]*c1.x + w[4]*c1.y + w[5]*r1
                        + w[6]*c2.x + w[7]*c2.y + w[8]*r2;
        float v0 = (a0 > 0.f) ? (a0 + 1.f) : __expf(a0);
        float v1 = (a1 > 0.f) ? (a1 + 1.f) : __expf(a1);

        // rope (in-thread pair)
        float r0v = v0*cs.x - v1*cs.y;
        float r1v = v0*cs.y + v1*cs.x;

        if (isK) {
            ksum0 += v0; ksum1 += v1;
            const float4* vp = &vsm[(2*ii + p)*16 + h*4];
            float4 va = vp[0], vb2 = vp[1], vc3 = vp[2], vd = vp[3];
            acc0[0] += r0v*va.x;  acc0[1] += r0v*va.y;  acc0[2] += r0v*va.z;  acc0[3] += r0v*va.w;
            acc0[4] += r0v*vb2.x; acc0[5] += r0v*vb2.y; acc0[6] += r0v*vb2.z; acc0[7] += r0v*vb2.w;
            acc0[8] += r0v*vc3.x; acc0[9] += r0v*vc3.y; acc0[10]+= r0v*vc3.z; acc0[11]+= r0v*vc3.w;
            acc0[12]+= r0v*vd.x;  acc0[13]+= r0v*vd.y;  acc0[14]+= r0v*vd.z;  acc0[15]+= r0v*vd.w;
            acc1[0] += r1v*va.x;  acc1[1] += r1v*va.y;  acc1[2] += r1v*va.z;  acc1[3] += r1v*va.w;
            acc1[4] += r1v*vb2.x; acc1[5] += r1v*vb2.y; acc1[6] += r1v*vb2.z; acc1[7] += r1v*vb2.w;
            acc1[8] += r1v*vc3.x; acc1[9] += r1v*vc3.y; acc1[10]+= r1v*vc3.z; acc1[11]+= r1v*vc3.w;
            acc1[12]+= r1v*vd.x;  acc1[13]+= r1v*vd.y;  acc1[14]+= r1v*vd.z;  acc1[15]+= r1v*vd.w;
        } else {
            *(float2*)qdst = make_float2(r0v, r1v);
            qdst += 128;     // next row of this parity: ni += 2
        }

        // advance rope phase; slide window; materialize pending; refill raw
        CSROT(cs, rot);
        l0=l1; c0=c1; r0=r1;  l1=l2; c1=c2; r1=r2;
        MAT(rA, rAl, rAr, l2, c2, r2);
        LDRAW(hi+3, rA, rAl, rAr);
    }

    __syncthreads();    // vsm dead everywhere before aliasing as sred
    if (isK) {
#pragma unroll
        for (int e = 0; e < 16; e++) {
            sred[e*64      + p*32 + j] = acc0[e];
            sred[(16+e)*64 + p*32 + j] = acc1[e];
        }
        sred2[p*64 + 2*j]     = ksum0;
        sred2[p*64 + 2*j + 1] = ksum1;
    }
    __syncthreads();
#pragma unroll
    for (int q = 0; q < 8; q++) {
        int s2 = t*8 + q;
        int idx = s2 >> 5, jv = s2 & 31;
        float v = sred[idx*64 + jv] + sred[idx*64 + 32 + jv];
        int d = 2*(jv & 7) + (idx >> 4);
        int e = idx & 15;
        int hh = jv >> 3;
        atomicAdd(&g_kv[b*1024 + hh*256 + d*16 + e], v);
    }
    if (t < 64) {
        atomicAdd(&g_ksum[b*64 + t], sred2[t] + sred2[64 + t]);
    }
}

// ---------------------------------------------------------------------------
// Pass 2 (per-batch launch): stream rope'd Q rows, z via rotated-ksum
// recurrence, matvec vs float2 kv REGISTERS, lepe 3x3 depth-1 sliding window,
// staged coalesced transpose write. No conv.
__global__ void __launch_bounds__(128) k3b_out(
    const float* __restrict__ x,
    const float* __restrict__ lepe_w,
    const float* __restrict__ lepe_b,
    float* __restrict__ out,
    int b)
{
    const int seg = blockIdx.x, ch = blockIdx.y;
    const int t = threadIdx.x;
    const int lane = t & 31;            // j
    const int w_id = t >> 5;
    const int s = w_id & 1, rg = w_id >> 1;
    const int j = lane;
    const int h = j >> 3, e0 = 2*(j & 7);
    const float* xb = x + (size_t)b * (64*NPIX);

    const float ks0 = __ldg(&g_ksum[b*64 + 2*j]);
    const float ks1 = __ldg(&g_ksum[b*64 + 2*j + 1]);
    float2 kv2[16];
#pragma unroll
    for (int d = 0; d < 16; d++)
        kv2[d] = __ldg((const float2*)&g_kv[b*1024 + h*256 + d*16 + e0]);

    float lw0[9], lw1[9];
#pragma unroll
    for (int i = 0; i < 9; i++) {
        lw0[i] = __ldg(&lepe_w[(2*j)*9 + i]);
        lw1[i] = __ldg(&lepe_w[(2*j+1)*9 + i]);
    }
    const float lb0 = __ldg(&lepe_b[2*j]);
    const float lb1 = __ldg(&lepe_b[2*j + 1]);

    __shared__ __align__(16) float qs[4][2][64];
    __shared__ float res[2][64][66];

    const int rs = seg*64 + rg*32;

    // q stream: rows ni = ch*512 + 2*hi + s, hi = rs..rs+31 (stride 128 floats)
    const float* qsrc = g_q + ((size_t)b*NPIX + (size_t)ch*512 + 2*rs + s)*64 + 2*j;
    float2 qv = __ldg((const float2*)qsrc);

    // rotated ksum via rotation recurrence: rks(col) = R(col) * ksum
    const int col0 = (2*rs + s) & 255;
    float2 cs  = __ldg(&g_cs[col0*32 + j]);
    const float2 rot = __ldg(&g_cs[2*32 + j]);
    float rks0 = cs.x*ks0 - cs.y*ks1;
    float rks1 = cs.y*ks0 + cs.x*ks1;

    // lepe geometry: warp covers cols col0 + 2*ii of image row R
    const int R = 2*ch + (rs >> 7);
    const bool rv0 = (R >= 1), rv2 = (R <= 254);
    const float* lp0 = xb + ((size_t)(R-1)*256)*64 + 2*j;
    const float* lp1 = xb + ((size_t)(R  )*256)*64 + 2*j;
    const float* lp2 = xb + ((size_t)(R+1)*256)*64 + 2*j;

#define LPLD(rp, rv, cc) ((rv && (unsigned)(cc) < 256u) ? \
        __ldg((const float2*)((rp) + (size_t)(cc)*64)) : make_float2(0.f,0.f))

    float2 M0 = LPLD(lp0, rv0, col0-1), M1 = LPLD(lp1, true, col0-1), M2 = LPLD(lp2, rv2, col0-1);
    float2 C0 = LPLD(lp0, rv0, col0),   C1 = LPLD(lp1, true, col0),   C2 = LPLD(lp2, rv2, col0);
    float2 P0 = LPLD(lp0, rv0, col0+1), P1 = LPLD(lp1, true, col0+1), P2 = LPLD(lp2, rv2, col0+1);

    for (int ii = 0; ii < 32; ii++) {
        const int col = col0 + 2*ii;
        // prefetch next q row (CLAMPED on last iteration), lepe cols
        const int qoff = (ii + 1 < 32) ? 128 : 0;
        float2 qv_n = __ldg((const float2*)(qsrc + qoff));
        float2 N0a = LPLD(lp0, rv0, col+2), N1a = LPLD(lp1, true, col+2), N2a = LPLD(lp2, rv2, col+2);
        float2 N0b = LPLD(lp0, rv0, col+3), N1b = LPLD(lp1, true, col+3), N2b = LPLD(lp2, rv2, col+3);

        // z: qrope . rks, 8-lane segment reduce
        float zp = qv.x*rks0 + qv.y*rks1;
        zp += __shfl_xor_sync(FULL, zp, 1);
        zp += __shfl_xor_sync(FULL, zp, 2);
        zp += __shfl_xor_sync(FULL, zp, 4);
        float z = 1.f / (zp * INV_N + 1e-6f);

        const int buf = ii & 1;
        *(float2*)&qs[w_id][buf][2*j] = qv;
        __syncwarp();
        const float4* qp = (const float4*)&qs[w_id][buf][h*16];
        float4 qa = qp[0], qb2 = qp[1], qc3 = qp[2], qd = qp[3];

        float o0 = qa.x*kv2[0].x  + qa.y*kv2[1].x  + qa.z*kv2[2].x  + qa.w*kv2[3].x
                 + qb2.x*kv2[4].x + qb2.y*kv2[5].x + qb2.z*kv2[6].x + qb2.w*kv2[7].x
                 + qc3.x*kv2[8].x + qc3.y*kv2[9].x + qc3.z*kv2[10].x+ qc3.w*kv2[11].x
                 + qd.x*kv2[12].x + qd.y*kv2[13].x + qd.z*kv2[14].x + qd.w*kv2[15].x;
        float o1 = qa.x*kv2[0].y  + qa.y*kv2[1].y  + qa.z*kv2[2].y  + qa.w*kv2[3].y
                 + qb2.x*kv2[4].y + qb2.y*kv2[5].y + qb2.z*kv2[6].y + qb2.w*kv2[7].y
                 + qc3.x*kv2[8].y + qc3.y*kv2[9].y + qc3.z*kv2[10].y+ qc3.w*kv2[11].y
                 + qd.x*kv2[12].y + qd.y*kv2[13].y + qd.z*kv2[14].y + qd.w*kv2[15].y;
        float zz = z * INV_N;
        o0 *= zz; o1 *= zz;

        // lepe taps at (R, col), channels 2j (x) and 2j+1 (y)
        o0 += lb0 + lw0[0]*M0.x + lw0[1]*C0.x + lw0[2]*P0.x
                  + lw0[3]*M1.x + lw0[4]*C1.x + lw0[5]*P1.x
                  + lw0[6]*M2.x + lw0[7]*C2.x + lw0[8]*P2.x;
        o1 += lb1 + lw1[0]*M0.y + lw1[1]*C0.y + lw1[2]*P0.y
                  + lw1[3]*M1.y + lw1[4]*C1.y + lw1[5]*P1.y
                  + lw1[6]*M2.y + lw1[7]*C2.y + lw1[8]*P2.y;

        const int pos = 2*(rg*32 + ii) + s;     // 0..127
        const int chunk = pos >> 6, p2 = pos & 63;
        res[chunk][2*j][p2]   = o0;
        res[chunk][2*j+1][p2] = o1;

        // advance rks by 2 columns; slide lepe window
        {
            float nr0 = rks0*rot.x - rks1*rot.y;
            rks1 = rks0*rot.y + rks1*rot.x;
            rks0 = nr0;
        }
        M0 = P0;  M1 = P1;  M2 = P2;
        C0 = N0a; C1 = N1a; C2 = N2a;
        P0 = N0b; P1 = N1b; P2 = N2b;

        qv = qv_n; qsrc += 128;
    }
#undef LPLD

    __syncthreads();
    float* ob = out + (size_t)b * (64*NPIX);
    const int nbase = ch*512 + seg*128;
    for (int ci = w_id; ci < 64; ci += 4) {
        float2 v0 = *(const float2*)&res[0][ci][2*lane];
        float2 v1 = *(const float2*)&res[1][ci][2*lane];
        *(float2*)&ob[(size_t)ci*NPIX + nbase + 2*lane]      = v0;
        *(float2*)&ob[(size_t)ci*NPIX + nbase + 64 + 2*lane] = v1;
    }
}

// ---------------------------------------------------------------------------
// Dual-stream pipelined launch: k3b(b) runs on a second stream, gated on
// k1(b) completion via events (standard capture fork/join). Streams/events
// are created once (host-side setup only; identical work enqueued per call).
extern "C" void kernel_launch(void* const* d_in, const int* in_sizes, int n_in,
                              void* d_out, int out_size) {
    (void)in_sizes; (void)n_in; (void)out_size;
    const float* x      = (const float*)d_in[0];
    const float* qk_w   = (const float*)d_in[1];
    const float* qk_b   = (const float*)d_in[2];
    const float* lepe_w = (const float*)d_in[3];
    const float* lepe_b = (const float*)d_in[4];
    float* out = (float*)d_out;

    static cudaStream_t s2 = nullptr;
    static cudaEvent_t  ev[BATCH + 1];
    if (s2 == nullptr) {
        cudaStreamCreateWithFlags(&s2, cudaStreamNonBlocking);
        for (int i = 0; i <= BATCH; i++)
            cudaEventCreateWithFlags(&ev[i], cudaEventDisableTiming);
    }

    k0_init<<<32, 256>>>();
    for (int b = 0; b < BATCH; b++) {
        k1_qkv<<<dim3(4, 128), 128>>>(x, qk_w, qk_b, b);
        cudaEventRecord(ev[b], 0);
    }
    for (int b = 0; b < BATCH; b++) {
        cudaStreamWaitEvent(s2, ev[b], 0);
        k3b_out<<<dim3(4, 128), 128, 0, s2>>>(x, lepe_w, lepe_b, out, b);
    }
    cudaEventRecord(ev[BATCH], s2);
    cudaStreamWaitEvent(0, ev[BATCH], 0);
}

// round 17
// speedup vs baseline: 1.1527x; 1.1527x over previous
#include <cuda_runtime.h>

#define BATCH 8
#define NPIX 65536
#define INV_N (1.0f/65536.0f)
#define FULL 0xffffffffu
typedef unsigned long long u64;

// accumulators + rope table (reset/refilled every launch by k0 -> deterministic)
__device__ float  g_ksum[BATCH*64];     // [b][kchan]
__device__ float  g_kv[BATCH*1024];     // [b][h][d][e]
__device__ float2 g_cs[256*32];         // [wcoord][j] cos/sin
// rope'd Q scratch, (b, n, 64) row-major; fully overwritten by k1 every launch
__device__ float  g_q[(size_t)BATCH*NPIX*64];

// ---------------------------------------------------------------------------
__device__ __forceinline__ u64 pk2(float lo, float hi) {
    u64 r; asm("mov.b64 %0, {%1, %2};" : "=l"(r) : "f"(lo), "f"(hi)); return r;
}
__device__ __forceinline__ void upk2(u64 v, float& lo, float& hi) {
    asm("mov.b64 {%0, %1}, %2;" : "=f"(lo), "=f"(hi) : "l"(v));
}
__device__ __forceinline__ u64 fma2(u64 a, u64 b, u64 c) {
    u64 d; asm("fma.rn.f32x2 %0, %1, %2, %3;" : "=l"(d) : "l"(a), "l"(b), "l"(c));
    return d;
}

// ---------------------------------------------------------------------------
__global__ void k0_init() {
    int t = blockIdx.x * 256 + threadIdx.x;     // 0..8191
    if (t < BATCH*64) g_ksum[t] = 0.f;
    g_kv[t] = 0.f;
    int wc = t >> 5, j = t & 31;
    float theta = exp2f(-(float)j * (13.287712379549449f / 32.0f));
    float a = (float)wc * theta;
    g_cs[t] = make_float2(cosf(a), sinf(a));
}

// ---------------------------------------------------------------------------
// Raw row load (no shfl at load time). Thread owns columns (COLV, COLV+1).
#define LDRAW(rr, RAW, EL, ER) do {                                            \
    int _r = (rr); bool _ok = ((unsigned)_r < 256u);                           \
    RAW = make_float2(0.f, 0.f); EL = 0.f; ER = 0.f;                           \
    if (_ok) {                                                                 \
        RAW = __ldg((const float2*)&xc[_r*256 + COLV]);                        \
        if (lane == 0 && LOKC)  EL = __ldg(&xc[_r*256 + COLV - 1]);            \
        if (lane == 31 && ROKC) ER = __ldg(&xc[_r*256 + COLV + 2]);            \
    } } while(0)

// Materialize (l, c, r) from a raw row at consumption time (shfl here).
#define MAT(RAW, EL, ER, L, C, R) do {                                         \
    float _l = __shfl_up_sync(FULL, RAW.y, 1);                                 \
    float _rv = __shfl_down_sync(FULL, RAW.x, 1);                              \
    if (lane == 0)  _l = EL;                                                   \
    if (lane == 31) _rv = ER;                                                  \
    (L) = _l; (C) = RAW; (R) = _rv; } while(0)

// complex rotation step: cs *= rot
#define CSROT(cs, rot) do {                                                    \
    float _x = cs.x*rot.x - cs.y*rot.y;                                        \
    cs.y = cs.x*rot.y + cs.y*rot.x;                                            \
    cs.x = _x; } while(0)

// ---------------------------------------------------------------------------
// Pass 1 (fused Q+K): one conv sweep per image-row quarter.
// Warps 0/2: Q halves -> elu, rope, stream to g_q.
// Warps 1/3: K halves -> elu, rope, kv accumulation via PACKED f32x2 FMA.
// Depth-1 raw row deferral; reduction buffers ALIAS vsm (dead after loop).
__global__ void __launch_bounds__(128) k1_qkv(
    const float* __restrict__ x,
    const float* __restrict__ qk_w,
    const float* __restrict__ qk_b)
{
    const int seg = blockIdx.x, ch = blockIdx.y, b = blockIdx.z;
    const int t = threadIdx.x;
    const int lane = t & 31;            // j: channel pair index
    const int w_id = t >> 5;
    const int p   = w_id >> 1;          // row parity (column half)
    const int isK = w_id & 1;
    const int j = lane;
    const int h = j >> 3;
    const float* xb = x + (size_t)b * (64*NPIX);
    const float* xc = xb + (size_t)(ch >> 1) * NPIX;

    const int COLV = p*128 + (isK ? 64 : 0) + 2*j;
    const bool LOKC = (COLV > 0);
    const bool ROKC = (COLV + 2 < 256);

    // V staging (32KB); reduction buffers alias it after the loop.
    __shared__ __align__(16) float4 vsm[2048];
    float* sred  = (float*)vsm;          // [32*64]
    float* sred2 = ((float*)vsm) + 2048; // [128]
    {
        const float4* vsrc = (const float4*)(xb + (size_t)ch*32768 + (size_t)seg*8192);
        for (int i = t; i < 2048; i += 128) vsm[i] = __ldg(vsrc + i);
    }

    float w[9];
#pragma unroll
    for (int i = 0; i < 9; i++) w[i] = __ldg(&qk_w[ch*9 + i]);
    const float bias = __ldg(&qk_b[ch]);

    const int rs = seg * 64;

    float l0,r0,l1,r1,l2,r2; float2 c0,c1,c2;
    float2 rA; float rAl, rAr;
    {
        float2 rw; float el, er;
        LDRAW(rs-1, rw, el, er); MAT(rw, el, er, l0, c0, r0);
        LDRAW(rs,   rw, el, er); MAT(rw, el, er, l1, c1, r1);
        LDRAW(rs+1, rw, el, er); MAT(rw, el, er, l2, c2, r2);
        LDRAW(rs+2, rA, rAl, rAr);
    }

    float2 cs  = __ldg(&g_cs[((2*rs + p) & 255)*32 + j]);
    const float2 rot = __ldg(&g_cs[2*32 + j]);

    // packed accumulators: accA[e2] = (acc0[2e2], acc0[2e2+1]); accB for acc1
    u64 accA[8], accB[8];
#pragma unroll
    for (int e = 0; e < 8; e++) { accA[e] = 0ull; accB[e] = 0ull; }
    float ksum0 = 0.f, ksum1 = 0.f;

    float* qdst = g_q + ((size_t)b*NPIX + (size_t)ch*512 + 2*rs + p)*64 + 2*j;

    __syncthreads();    // vsm ready

    for (int ii = 0; ii < 64; ii++) {
        const int hi = rs + ii;

        float a0 = bias + w[0]*l0   + w[1]*c0.x + w[2]*c0.y
                        + w[3]*l1   + w[4]*c1.x + w[5]*c1.y
                        + w[6]*l2   + w[7]*c2.x + w[8]*c2.y;
        float a1 = bias + w[0]*c0.x + w[1]*c0.y + w[2]*r0
                        + w[3]*c1.x + w[4]*c1.y + w[5]*r1
                        + w[6]*c2.x + w[7]*c2.y + w[8]*r2;
        float v0 = (a0 > 0.f) ? (a0 + 1.f) : __expf(a0);
        float v1 = (a1 > 0.f) ? (a1 + 1.f) : __expf(a1);

        // rope (in-thread pair)
        float r0v = v0*cs.x - v1*cs.y;
        float r1v = v0*cs.y + v1*cs.x;

        if (isK) {
            ksum0 += v0; ksum1 += v1;
            const ulonglong2* vp = (const ulonglong2*)&vsm[(2*ii + p)*16 + h*4];
            ulonglong2 u0 = vp[0], u1 = vp[1], u2 = vp[2], u3 = vp[3];
            u64 krA = pk2(r0v, r0v), krB = pk2(r1v, r1v);
            accA[0] = fma2(krA, u0.x, accA[0]);  accB[0] = fma2(krB, u0.x, accB[0]);
            accA[1] = fma2(krA, u0.y, accA[1]);  accB[1] = fma2(krB, u0.y, accB[1]);
            accA[2] = fma2(krA, u1.x, accA[2]);  accB[2] = fma2(krB, u1.x, accB[2]);
            accA[3] = fma2(krA, u1.y, accA[3]);  accB[3] = fma2(krB, u1.y, accB[3]);
            accA[4] = fma2(krA, u2.x, accA[4]);  accB[4] = fma2(krB, u2.x, accB[4]);
            accA[5] = fma2(krA, u2.y, accA[5]);  accB[5] = fma2(krB, u2.y, accB[5]);
            accA[6] = fma2(krA, u3.x, accA[6]);  accB[6] = fma2(krB, u3.x, accB[6]);
            accA[7] = fma2(krA, u3.y, accA[7]);  accB[7] = fma2(krB, u3.y, accB[7]);
        } else {
            *(float2*)qdst = make_float2(r0v, r1v);
            qdst += 128;     // next row of this parity: ni += 2
        }

        CSROT(cs, rot);
        l0=l1; c0=c1; r0=r1;  l1=l2; c1=c2; r1=r2;
        MAT(rA, rAl, rAr, l2, c2, r2);
        LDRAW(hi+3, rA, rAl, rAr);
    }

    // unpack accumulators
    float acc0[16], acc1[16];
#pragma unroll
    for (int e = 0; e < 8; e++) {
        upk2(accA[e], acc0[2*e], acc0[2*e+1]);
        upk2(accB[e], acc1[2*e], acc1[2*e+1]);
    }

    __syncthreads();    // vsm dead everywhere before aliasing as sred
    if (isK) {
#pragma unroll
        for (int e = 0; e < 16; e++) {
            sred[e*64      + p*32 + j] = acc0[e];
            sred[(16+e)*64 + p*32 + j] = acc1[e];
        }
        sred2[p*64 + 2*j]     = ksum0;
        sred2[p*64 + 2*j + 1] = ksum1;
    }
    __syncthreads();
#pragma unroll
    for (int q = 0; q < 8; q++) {
        int s2 = t*8 + q;
        int idx = s2 >> 5, jv = s2 & 31;
        float v = sred[idx*64 + jv] + sred[idx*64 + 32 + jv];
        int d = 2*(jv & 7) + (idx >> 4);
        int e = idx & 15;
        int hh = jv >> 3;
        atomicAdd(&g_kv[b*1024 + hh*256 + d*16 + e], v);
    }
    if (t < 64) {
        atomicAdd(&g_ksum[b*64 + t], sred2[t] + sred2[64 + t]);
    }
}

// ---------------------------------------------------------------------------
// Pass 2: stream rope'd Q rows, z via rotated-ksum recurrence, PACKED f32x2
// matvec + PACKED lepe, staged coalesced transpose write. No conv.
__global__ void __launch_bounds__(128) k3b_out(
    const float* __restrict__ x,
    const float* __restrict__ lepe_w,
    const float* __restrict__ lepe_b,
    float* __restrict__ out)
{
    const int seg = blockIdx.x, ch = blockIdx.y, b = blockIdx.z;
    const int t = threadIdx.x;
    const int lane = t & 31;            // j
    const int w_id = t >> 5;
    const int s = w_id & 1, rg = w_id >> 1;
    const int j = lane;
    const int h = j >> 3, e0 = 2*(j & 7);
    const float* xb = x + (size_t)b * (64*NPIX);

    const float ks0 = __ldg(&g_ksum[b*64 + 2*j]);
    const float ks1 = __ldg(&g_ksum[b*64 + 2*j + 1]);
    // kv packed: kvx[d2] = (kv[2d2].x, kv[2d2+1].x), kvy likewise
    u64 kvx[8], kvy[8];
#pragma unroll
    for (int d2 = 0; d2 < 8; d2++) {
        float2 a = __ldg((const float2*)&g_kv[b*1024 + h*256 + (2*d2)*16 + e0]);
        float2 c = __ldg((const float2*)&g_kv[b*1024 + h*256 + (2*d2+1)*16 + e0]);
        kvx[d2] = pk2(a.x, c.x);
        kvy[d2] = pk2(a.y, c.y);
    }

    // lepe weights packed: lwp[i] = (lw0[i], lw1[i])
    u64 lwp[9];
#pragma unroll
    for (int i = 0; i < 9; i++)
        lwp[i] = pk2(__ldg(&lepe_w[(2*j)*9 + i]), __ldg(&lepe_w[(2*j+1)*9 + i]));
    const u64 lbp = pk2(__ldg(&lepe_b[2*j]), __ldg(&lepe_b[2*j + 1]));

    __shared__ __align__(16) float qs[4][2][64];
    __shared__ float res[2][64][66];

    const int rs = seg*64 + rg*32;

    const float* qsrc = g_q + ((size_t)b*NPIX + (size_t)ch*512 + 2*rs + s)*64 + 2*j;
    float2 qv = __ldg((const float2*)qsrc);

    const int col0 = (2*rs + s) & 255;
    float2 cs  = __ldg(&g_cs[col0*32 + j]);
    const float2 rot = __ldg(&g_cs[2*32 + j]);
    float rks0 = cs.x*ks0 - cs.y*ks1;
    float rks1 = cs.y*ks0 + cs.x*ks1;

    // lepe geometry: warp covers cols col0 + 2*ii of image row R
    const int R = 2*ch + (rs >> 7);
    const bool rv0 = (R >= 1), rv2 = (R <= 254);
    const float* lp0 = xb + ((size_t)(R-1)*256)*64 + 2*j;
    const float* lp1 = xb + ((size_t)(R  )*256)*64 + 2*j;
    const float* lp2 = xb + ((size_t)(R+1)*256)*64 + 2*j;

// packed (chan2j, chan2j+1) load of the v-image pixel
#define LPLD(rp, rv, cc) ((rv && (unsigned)(cc) < 256u) ? \
        __ldg((const u64*)((rp) + (size_t)(cc)*64)) : 0ull)

    u64 M0 = LPLD(lp0, rv0, col0-1), M1 = LPLD(lp1, true, col0-1), M2 = LPLD(lp2, rv2, col0-1);
    u64 C0 = LPLD(lp0, rv0, col0),   C1 = LPLD(lp1, true, col0),   C2 = LPLD(lp2, rv2, col0);
    u64 P0 = LPLD(lp0, rv0, col0+1), P1 = LPLD(lp1, true, col0+1), P2 = LPLD(lp2, rv2, col0+1);

    for (int ii = 0; ii < 32; ii++) {
        const int col = col0 + 2*ii;
        const int qoff = (ii + 1 < 32) ? 128 : 0;
        float2 qv_n = __ldg((const float2*)(qsrc + qoff));
        u64 N0a = LPLD(lp0, rv0, col+2), N1a = LPLD(lp1, true, col+2), N2a = LPLD(lp2, rv2, col+2);
        u64 N0b = LPLD(lp0, rv0, col+3), N1b = LPLD(lp1, true, col+3), N2b = LPLD(lp2, rv2, col+3);

        // z: qrope . rks, 8-lane segment reduce
        float zp = qv.x*rks0 + qv.y*rks1;
        zp += __shfl_xor_sync(FULL, zp, 1);
        zp += __shfl_xor_sync(FULL, zp, 2);
        zp += __shfl_xor_sync(FULL, zp, 4);
        float z = 1.f / (zp * INV_N + 1e-6f);

        const int buf = ii & 1;
        *(float2*)&qs[w_id][buf][2*j] = qv;
        __syncwarp();
        const ulonglong2* qp = (const ulonglong2*)&qs[w_id][buf][h*16];
        ulonglong2 qA = qp[0], qB = qp[1], qC = qp[2], qD = qp[3];

        // packed matvec: s0 accumulates o0 pairs, s1 accumulates o1 pairs
        u64 s0 = 0ull, s1 = 0ull;
        s0 = fma2(qA.x, kvx[0], s0);  s1 = fma2(qA.x, kvy[0], s1);
        s0 = fma2(qA.y, kvx[1], s0);  s1 = fma2(qA.y, kvy[1], s1);
        s0 = fma2(qB.x, kvx[2], s0);  s1 = fma2(qB.x, kvy[2], s1);
        s0 = fma2(qB.y, kvx[3], s0);  s1 = fma2(qB.y, kvy[3], s1);
        s0 = fma2(qC.x, kvx[4], s0);  s1 = fma2(qC.x, kvy[4], s1);
        s0 = fma2(qC.y, kvx[5], s0);  s1 = fma2(qC.y, kvy[5], s1);
        s0 = fma2(qD.x, kvx[6], s0);  s1 = fma2(qD.x, kvy[6], s1);
        s0 = fma2(qD.y, kvx[7], s0);  s1 = fma2(qD.y, kvy[7], s1);
        float s0a, s0b, s1a, s1b;
        upk2(s0, s0a, s0b);
        upk2(s1, s1a, s1b);
        float zz = z * INV_N;
        float o0 = (s0a + s0b) * zz;
        float o1 = (s1a + s1b) * zz;

        // packed lepe: lp accumulates (lepe0, lepe1)
        u64 le = lbp;
        le = fma2(lwp[0], M0, le);
        le = fma2(lwp[1], C0, le);
        le = fma2(lwp[2], P0, le);
        le = fma2(lwp[3], M1, le);
        le = fma2(lwp[4], C1, le);
        le = fma2(lwp[5], P1, le);
        le = fma2(lwp[6], M2, le);
        le = fma2(lwp[7], C2, le);
        le = fma2(lwp[8], P2, le);
        float le0, le1;
        upk2(le, le0, le1);
        o0 += le0; o1 += le1;

        const int pos = 2*(rg*32 + ii) + s;     // 0..127
        const int chunk = pos >> 6, p2 = pos & 63;
        res[chunk][2*j][p2]   = o0;
        res[chunk][2*j+1][p2] = o1;

        // advance rks by 2 columns; slide lepe window
        {
            float nr0 = rks0*rot.x - rks1*rot.y;
            rks1 = rks0*rot.y + rks1*rot.x;
            rks0 = nr0;
        }
        M0 = P0;  M1 = P1;  M2 = P2;
        C0 = N0a; C1 = N1a; C2 = N2a;
        P0 = N0b; P1 = N1b; P2 = N2b;

        qv = qv_n; qsrc += 128;
    }
#undef LPLD

    __syncthreads();
    float* ob = out + (size_t)b * (64*NPIX);
    const int nbase = ch*512 + seg*128;
    for (int ci = w_id; ci < 64; ci += 4) {
        float2 v0 = *(const float2*)&res[0][ci][2*lane];
        float2 v1 = *(const float2*)&res[1][ci][2*lane];
        *(float2*)&ob[(size_t)ci*NPIX + nbase + 2*lane]      = v0;
        *(float2*)&ob[(size_t)ci*NPIX + nbase + 64 + 2*lane] = v1;
    }
}

// ---------------------------------------------------------------------------
extern "C" void kernel_launch(void* const* d_in, const int* in_sizes, int n_in,
                              void* d_out, int out_size) {
    (void)in_sizes; (void)n_in; (void)out_size;
    const float* x      = (const float*)d_in[0];
    const float* qk_w   = (const float*)d_in[1];
    const float* qk_b   = (const float*)d_in[2];
    const float* lepe_w = (const float*)d_in[3];
    const float* lepe_b = (const float*)d_in[4];
    float* out = (float*)d_out;

    k0_init<<<32, 256>>>();
    k1_qkv<<<dim3(4, 128, BATCH), 128>>>(x, qk_w, qk_b);
    k3b_out<<<dim3(4, 128, BATCH), 128>>>(x, lepe_w, lepe_b, out);
}